// round 9
// baseline (speedup 1.0000x reference)
#include <cuda_runtime.h>
#include <cstdint>

// ---------------------------------------------------------------------------
// out[n,o,h,w] = sum_{c,kw} x[n,c,(h-1)%56, w+kw-1] * wgt[o,c,kw]
// N=128, C=128, H=W=56, O=32, KW=3 (pad W by 1 each side).
// v3: per (n,h) GEMM C[32,56] = W[32,384] * X[384,56] via mma.sync.m16n8k8
// tf32. x rows staged in smem (stride-72 -> conflict-free LDS B windows);
// A (weight) fragments prebuilt ONCE by a prep kernel into a __device__
// global (tf32 bits, per-lane uint4 order) and read via __ldg (L1-resident,
// shared by all CTAs). smem/CTA = 72KB -> 3 CTAs/SM (24 warps) with
// 1-wavefront B loads.
// ---------------------------------------------------------------------------

namespace {

constexpr int ROWS_PER_BLK = 2;                    // (n,h) rows per block
constexpr int XSTRIDE      = 72;                   // 72 % 32 == 8 -> conflict-free
constexpr int XS_PER_ROW   = 128 * XSTRIDE;        // 9216 floats
constexpr int XS_FLOATS    = ROWS_PER_BLK * XS_PER_ROW;  // 18432 floats = 72KB
constexpr int SMEM_BYTES   = XS_FLOATS * 4;
constexpr int AFR_U32      = 3 * 2 * 16 * 32 * 4;  // kw*mtile*ks*lane*4 = 12288
constexpr int CH_STRIDE    = 56 * 56;

__device__ __align__(16) unsigned g_afr[AFR_U32];  // 48KB weight-fragment table

__device__ __forceinline__ unsigned f2tf32(float f) {
    unsigned u;
    asm("cvt.rna.tf32.f32 %0, %1;" : "=r"(u) : "f"(f));
    return u;
}

__device__ __forceinline__ void mma_tf32(float d[4], const uint4& a,
                                         float b0f, float b1f) {
    unsigned b0 = __float_as_uint(b0f);
    unsigned b1 = __float_as_uint(b1f);
    asm volatile(
        "mma.sync.aligned.m16n8k8.row.col.f32.tf32.tf32.f32 "
        "{%0,%1,%2,%3}, {%4,%5,%6,%7}, {%8,%9}, {%0,%1,%2,%3};"
        : "+f"(d[0]), "+f"(d[1]), "+f"(d[2]), "+f"(d[3])
        : "r"(a.x), "r"(a.y), "r"(a.z), "r"(a.w), "r"(b0), "r"(b1));
}

} // namespace

// --- prep: build weight fragments in per-lane uint4 order -------------------
// e = reg + 4*lane + 128*ks + 2048*m + 4096*kw
__global__ void build_afr(const float* __restrict__ wgt) {
    int e = blockIdx.x * 256 + threadIdx.x;
    if (e >= AFR_U32) return;
    int rr   = e & 3;
    int lane = (e >> 2) & 31;
    int ks   = (e >> 7) & 15;
    int m    = (e >> 11) & 1;
    int kw   = e >> 12;
    // m16n8k8 A frag: a0=(g,t) a1=(g+8,t) a2=(g,t+4) a3=(g+8,t+4)
    int o = m * 16 + (lane >> 2) + ((rr & 1) << 3);
    int c = ks * 8 + (lane & 3) + ((rr & 2) << 1);
    g_afr[e] = f2tf32(wgt[(o * 128 + c) * 3 + kw]);
}

__global__ __launch_bounds__(256, 3)
void conv1x3_shift_tf32_v3(const float* __restrict__ x,
                           float* __restrict__ out) {
    extern __shared__ float xs[];      // staged x rows, stride 72, offset +1

    const int tid = threadIdx.x;
    const int blk = blockIdx.x;

    // --- zero pad columns (w = -1 -> idx 0, w = 56 -> idx 57) --------------
    for (int p = tid; p < ROWS_PER_BLK * 128; p += 256) {
        xs[p * XSTRIDE + 0]  = 0.f;
        xs[p * XSTRIDE + 57] = 0.f;
    }

    // --- stage 2 x rows: x[n, c, hsrc, 0..55] -> xs[r][c][1..56] -----------
    for (int i = tid; i < ROWS_PER_BLK * 128 * 14; i += 256) {
        int r    = i / (128 * 14);
        int rem  = i - r * (128 * 14);
        int c    = rem / 14;
        int q    = rem - c * 14;
        int R    = blk * ROWS_PER_BLK + r;
        int n    = R / 56;
        int h    = R - n * 56;
        int hsrc = h ? (h - 1) : 55;   // roll(+1) on H
        const float4 v = *reinterpret_cast<const float4*>(
            x + ((size_t)(n * 128 + c) * 56 + hsrc) * 56 + q * 4);
        float* dst = xs + (r * 128 + c) * XSTRIDE + 1 + q * 4;
        dst[0] = v.x; dst[1] = v.y; dst[2] = v.z; dst[3] = v.w;
    }
    __syncthreads();

    // --- warp = (row r, quarter q). warp q owns w-tiles {2q, 2q+1} ---------
    const int warp = tid >> 5;
    const int lane = tid & 31;
    const int r    = warp >> 2;        // 0..1
    const int q4   = warp & 3;         // 0..3
    const int g    = lane >> 2;        // 0..7
    const int t    = lane & 3;         // 0..3

    const int ntile = (q4 == 3) ? 1 : 2;   // tile 7 doesn't exist (W=56)

    int wcol[2];
    #pragma unroll
    for (int j = 0; j < 2; j++) wcol[j] = g + 8 * (2 * q4 + j);

    float acc[2][2][4];
    #pragma unroll
    for (int m = 0; m < 2; m++)
        #pragma unroll
        for (int j = 0; j < 2; j++)
            #pragma unroll
            for (int v = 0; v < 4; v++) acc[m][j][v] = 0.f;

    const float* xrow = xs + r * XS_PER_ROW;
    const uint4* afp  = reinterpret_cast<const uint4*>(g_afr);

    #pragma unroll 4
    for (int ks = 0; ks < 16; ks++) {
        // B window: 3 consecutive smem floats per (kr, j); bank-conflict-free
        float xv[2][2][3];
        #pragma unroll
        for (int kr = 0; kr < 2; kr++) {
            const float* pr = xrow + (ks * 8 + t + kr * 4) * XSTRIDE;
            #pragma unroll
            for (int j = 0; j < 2; j++) {
                if (j >= ntile) continue;
                const float* p = pr + wcol[j];   // idx wcol = w-1 (pad at 0)
                xv[kr][j][0] = p[0];
                xv[kr][j][1] = p[1];
                xv[kr][j][2] = p[2];
            }
        }
        #pragma unroll
        for (int kw = 0; kw < 3; kw++) {
            uint4 a0 = __ldg(&afp[((kw * 2 + 0) * 16 + ks) * 32 + lane]);
            uint4 a1 = __ldg(&afp[((kw * 2 + 1) * 16 + ks) * 32 + lane]);
            #pragma unroll
            for (int j = 0; j < 2; j++) {
                if (j >= ntile) continue;
                mma_tf32(acc[0][j], a0, xv[0][j][kw], xv[1][j][kw]);
                mma_tf32(acc[1][j], a1, xv[0][j][kw], xv[1][j][kw]);
            }
        }
    }

    // --- epilogue: C frag c0=(g,2t) c1=(g,2t+1) c2=(g+8,2t) c3=(g+8,2t+1) --
    {
        int R = blk * ROWS_PER_BLK + r;
        int n = R / 56;
        int h = R - n * 56;
        #pragma unroll
        for (int m = 0; m < 2; m++) {
            int o0 = m * 16 + g;
            #pragma unroll
            for (int j = 0; j < 2; j++) {
                if (j >= ntile) continue;
                int wc = 8 * (2 * q4 + j) + 2 * t;   // even, < 56
                float* p0 = out + ((size_t)n * 32 + o0) * CH_STRIDE + h * 56 + wc;
                *reinterpret_cast<float2*>(p0) =
                    make_float2(acc[m][j][0], acc[m][j][1]);
                float* p1 = p0 + 8 * CH_STRIDE;       // o0 + 8
                *reinterpret_cast<float2*>(p1) =
                    make_float2(acc[m][j][2], acc[m][j][3]);
            }
        }
    }
}

extern "C" void kernel_launch(void* const* d_in, const int* in_sizes, int n_in,
                              void* d_out, int out_size) {
    const float* x   = (const float*)d_in[0];   // (128,128,56,56) f32
    const float* wgt = (const float*)d_in[1];   // (32,128,3) f32
    float*       out = (float*)d_out;           // (128,32,56,56) f32

    cudaFuncSetAttribute(conv1x3_shift_tf32_v3,
                         cudaFuncAttributeMaxDynamicSharedMemorySize,
                         SMEM_BYTES);

    build_afr<<<(AFR_U32 + 255) / 256, 256>>>(wgt);
    // 7168 (n,h) rows / 2 rows per block = 3584 blocks
    conv1x3_shift_tf32_v3<<<3584, 256, SMEM_BYTES>>>(x, out);
}

// round 12
// speedup vs baseline: 1.4691x; 1.4691x over previous
#include <cuda_runtime.h>
#include <cuda_fp16.h>
#include <cstdint>

// ---------------------------------------------------------------------------
// out[n,o,h,w] = sum_{c,kw} x[n,c,(h-1)%56, w+kw-1] * wgt[o,c,kw]
// N=128, C=128, H=W=56, O=32, KW=3 (pad W by 1 each side).
// v4: fp16 mma.sync.m16n8k16 (f32 accum). x staged in smem as half2
// CHANNEL PAIRS: xs[c2][w] = (x[2c2][w], x[2c2+1][w]) -> one LDS.32 is a
// complete B register. Row stride 72 half2 (=8 mod 32 banks) -> conflict-free.
// A (weight) fragments prebuilt once (prep kernel) into a 24KB __device__
// table, copied to smem per CTA. smem = 36KB x + 24KB A = 60KB -> 3 CTAs/SM.
// fp16 mantissa == tf32 mantissa -> same rel_err (~4.7e-4), half the mma
// count and half the l1tex traffic per FLOP.
// ---------------------------------------------------------------------------

namespace {

constexpr int ROWS_PER_BLK = 2;                 // (n,h) rows per block
constexpr int WSTRIDE      = 72;                // half2 units per c2-row (72%32==8)
constexpr int XS_H2_ROW    = 64 * WSTRIDE;      // 4608 half2 per (n,h) row
constexpr int XS_BYTES     = ROWS_PER_BLK * XS_H2_ROW * 4;   // 36864
constexpr int AFR_U4       = 3 * 2 * 8 * 32;    // kw * mtile * ks * lane = 1536
constexpr int AFR_BYTES    = AFR_U4 * 16;       // 24576
constexpr int SMEM_BYTES   = XS_BYTES + AFR_BYTES;           // 61440
constexpr int CH_STRIDE    = 56 * 56;           // 3136

__device__ __align__(16) uint4 g_afr[AFR_U4];   // weight fragments (fp16 bits)

__device__ __forceinline__ unsigned h2bits(__half2 h) {
    return *reinterpret_cast<unsigned*>(&h);
}

__device__ __forceinline__ void mma_f16(float d[4], const uint4& a,
                                        unsigned b0, unsigned b1) {
    asm volatile(
        "mma.sync.aligned.m16n8k16.row.col.f32.f16.f16.f32 "
        "{%0,%1,%2,%3}, {%4,%5,%6,%7}, {%8,%9}, {%0,%1,%2,%3};"
        : "+f"(d[0]), "+f"(d[1]), "+f"(d[2]), "+f"(d[3])
        : "r"(a.x), "r"(a.y), "r"(a.z), "r"(a.w), "r"(b0), "r"(b1));
}

} // namespace

// --- prep: build fp16 A fragments in per-lane uint4 order -------------------
// uint4 index e = ((kw*2 + m)*8 + ks)*32 + lane
// m16n8k16 A frag (row o, col c=k): a0=(g, 2t|2t+1) a1=(g+8, ..)
//                                   a2=(g, 2t+8|2t+9) a3=(g+8, ..)
__global__ void build_afr16(const float* __restrict__ wgt) {
    int e = blockIdx.x * 256 + threadIdx.x;
    if (e >= AFR_U4) return;
    int lane = e & 31;
    int ks   = (e >> 5) & 7;
    int m    = (e >> 8) & 1;
    int kw   = e >> 9;
    int g = lane >> 2, t = lane & 3;
    int o0 = m * 16 + g;
    int c0 = ks * 16 + 2 * t;
    auto W = [&](int o, int c) {
        return __float2half_rn(wgt[(o * 128 + c) * 3 + kw]);
    };
    __half2 a0 = __halves2half2(W(o0,     c0),     W(o0,     c0 + 1));
    __half2 a1 = __halves2half2(W(o0 + 8, c0),     W(o0 + 8, c0 + 1));
    __half2 a2 = __halves2half2(W(o0,     c0 + 8), W(o0,     c0 + 9));
    __half2 a3 = __halves2half2(W(o0 + 8, c0 + 8), W(o0 + 8, c0 + 9));
    g_afr[e] = make_uint4(h2bits(a0), h2bits(a1), h2bits(a2), h2bits(a3));
}

__global__ __launch_bounds__(256, 3)
void conv1x3_shift_f16_v4(const float* __restrict__ x,
                          float* __restrict__ out) {
    extern __shared__ char smem[];
    __half2* xs  = reinterpret_cast<__half2*>(smem);            // [2][64][72]
    uint4*   afs = reinterpret_cast<uint4*>(smem + XS_BYTES);   // [1536]

    const int tid = threadIdx.x;
    const int blk = blockIdx.x;

    // --- copy A table to smem (L2-resident after first CTA) ----------------
    for (int e = tid; e < AFR_U4; e += 256) afs[e] = g_afr[e];

    // --- zero pad slots: idx 3 (w=-1) and idx 60 (w=56) --------------------
    for (int p = tid; p < ROWS_PER_BLK * 64; p += 256) {
        xs[p * WSTRIDE + 3]  = __float2half2_rn(0.f);
        xs[p * WSTRIDE + 60] = __float2half2_rn(0.f);
    }

    // --- stage 2 x rows as half2 channel pairs; data at idx 4 + w ----------
    for (int i = tid; i < ROWS_PER_BLK * 64 * 14; i += 256) {
        int r    = i / (64 * 14);
        int rem  = i - r * (64 * 14);
        int c2   = rem / 14;
        int q    = rem - c2 * 14;
        int R    = blk * ROWS_PER_BLK + r;
        int n    = R / 56;
        int h    = R - n * 56;
        int hsrc = h ? (h - 1) : 55;   // roll(+1) on H
        const float* base =
            x + ((size_t)(n * 128 + 2 * c2) * 56 + hsrc) * 56 + 4 * q;
        float4 va = *reinterpret_cast<const float4*>(base);              // c even
        float4 vb = *reinterpret_cast<const float4*>(base + CH_STRIDE);  // c odd
        uint4 pk = make_uint4(h2bits(__floats2half2_rn(va.x, vb.x)),
                              h2bits(__floats2half2_rn(va.y, vb.y)),
                              h2bits(__floats2half2_rn(va.z, vb.z)),
                              h2bits(__floats2half2_rn(va.w, vb.w)));
        *reinterpret_cast<uint4*>(xs + (r * 64 + c2) * WSTRIDE + 4 + 4 * q) = pk;
    }
    __syncthreads();

    // --- warp = (row r, quarter q4); warp owns w-tiles {2q4, 2q4+1} --------
    const int warp = tid >> 5;
    const int lane = tid & 31;
    const int r    = warp >> 2;        // 0..1
    const int q4   = warp & 3;         // 0..3
    const int g    = lane >> 2;        // 0..7
    const int t    = lane & 3;         // 0..3

    const int ntile = (q4 == 3) ? 1 : 2;   // tile 7 doesn't exist (W=56)

    int wcol[2];
    #pragma unroll
    for (int j = 0; j < 2; j++) wcol[j] = g + 8 * (2 * q4 + j);

    float acc[2][2][4];
    #pragma unroll
    for (int m = 0; m < 2; m++)
        #pragma unroll
        for (int j = 0; j < 2; j++)
            #pragma unroll
            for (int v = 0; v < 4; v++) acc[m][j][v] = 0.f;

    const __half2* xrow = xs + r * XS_H2_ROW;

    #pragma unroll 2
    for (int ks = 0; ks < 8; ks++) {
        // B rows: b0 -> c2 = 8ks + t, b1 -> c2 = 8ks + t + 4.
        // smem idx = c2*WSTRIDE + 3 + wcol + kw  (bank = 8t + g + const: free)
        const __half2* p0 = xrow + (8 * ks + t) * WSTRIDE + 3;
        const __half2* p1 = p0 + 4 * WSTRIDE;

        unsigned bv0[2][3], bv1[2][3];
        #pragma unroll
        for (int j = 0; j < 2; j++) {
            if (j >= ntile) continue;
            #pragma unroll
            for (int kw = 0; kw < 3; kw++) {
                bv0[j][kw] = h2bits(p0[wcol[j] + kw]);
                bv1[j][kw] = h2bits(p1[wcol[j] + kw]);
            }
        }
        #pragma unroll
        for (int kw = 0; kw < 3; kw++) {
            uint4 a0 = afs[((kw * 2 + 0) * 8 + ks) * 32 + lane];
            uint4 a1 = afs[((kw * 2 + 1) * 8 + ks) * 32 + lane];
            #pragma unroll
            for (int j = 0; j < 2; j++) {
                if (j >= ntile) continue;
                mma_f16(acc[0][j], a0, bv0[j][kw], bv1[j][kw]);
                mma_f16(acc[1][j], a1, bv0[j][kw], bv1[j][kw]);
            }
        }
    }

    // --- epilogue: C frag c0=(g,2t) c1=(g,2t+1) c2=(g+8,2t) c3=(g+8,2t+1) --
    {
        int R = blk * ROWS_PER_BLK + r;
        int n = R / 56;
        int h = R - n * 56;
        #pragma unroll
        for (int m = 0; m < 2; m++) {
            int o0 = m * 16 + g;
            #pragma unroll
            for (int j = 0; j < 2; j++) {
                if (j >= ntile) continue;
                int wc = 8 * (2 * q4 + j) + 2 * t;   // even, < 56
                float* p0 = out + ((size_t)n * 32 + o0) * CH_STRIDE + h * 56 + wc;
                *reinterpret_cast<float2*>(p0) =
                    make_float2(acc[m][j][0], acc[m][j][1]);
                float* p1 = p0 + 8 * CH_STRIDE;       // o0 + 8
                *reinterpret_cast<float2*>(p1) =
                    make_float2(acc[m][j][2], acc[m][j][3]);
            }
        }
    }
}

extern "C" void kernel_launch(void* const* d_in, const int* in_sizes, int n_in,
                              void* d_out, int out_size) {
    const float* x   = (const float*)d_in[0];   // (128,128,56,56) f32
    const float* wgt = (const float*)d_in[1];   // (32,128,3) f32
    float*       out = (float*)d_out;           // (128,32,56,56) f32

    cudaFuncSetAttribute(conv1x3_shift_f16_v4,
                         cudaFuncAttributeMaxDynamicSharedMemorySize,
                         SMEM_BYTES);

    build_afr16<<<(AFR_U4 + 255) / 256, 256>>>(wgt);
    // 7168 (n,h) rows / 2 rows per block = 3584 blocks
    conv1x3_shift_f16_v4<<<3584, 256, SMEM_BYTES>>>(x, out);
}

// round 14
// speedup vs baseline: 1.5631x; 1.0639x over previous
#include <cuda_runtime.h>
#include <cuda_fp16.h>
#include <cstdint>

// ---------------------------------------------------------------------------
// out[n,o,h,w] = sum_{c,kw} x[n,c,(h-1)%56, w+kw-1] * wgt[o,c,kw]
// N=128, C=128, H=W=56, O=32, KW=3 (pad W by 1 each side).
// v5 = v4 (fp16 m16n8k16, channel-pair smem, smem A table) with the staging
// loop restructured for MLP: thread = (r, c2, qg) loads 7+7 CONSECUTIVE
// float4 (112B per plane) as one batch of 14 independent LDG.128s, then
// packs to half2 channel pairs with 7 conflict-free STS.128s.
// ---------------------------------------------------------------------------

namespace {

constexpr int ROWS_PER_BLK = 2;                 // (n,h) rows per block
constexpr int WSTRIDE      = 72;                // half2 per c2-row (72%32==8)
constexpr int XS_H2_ROW    = 64 * WSTRIDE;      // 4608 half2 per (n,h) row
constexpr int XS_BYTES     = ROWS_PER_BLK * XS_H2_ROW * 4;   // 36864
constexpr int AFR_U4       = 3 * 2 * 8 * 32;    // kw * mtile * ks * lane = 1536
constexpr int AFR_BYTES    = AFR_U4 * 16;       // 24576
constexpr int SMEM_BYTES   = XS_BYTES + AFR_BYTES;           // 61440
constexpr int CH_STRIDE    = 56 * 56;           // 3136

__device__ __align__(16) uint4 g_afr[AFR_U4];   // weight fragments (fp16 bits)

__device__ __forceinline__ unsigned h2bits(__half2 h) {
    return *reinterpret_cast<unsigned*>(&h);
}

__device__ __forceinline__ void mma_f16(float d[4], const uint4& a,
                                        unsigned b0, unsigned b1) {
    asm volatile(
        "mma.sync.aligned.m16n8k16.row.col.f32.f16.f16.f32 "
        "{%0,%1,%2,%3}, {%4,%5,%6,%7}, {%8,%9}, {%0,%1,%2,%3};"
        : "+f"(d[0]), "+f"(d[1]), "+f"(d[2]), "+f"(d[3])
        : "r"(a.x), "r"(a.y), "r"(a.z), "r"(a.w), "r"(b0), "r"(b1));
}

} // namespace

// --- prep: build fp16 A fragments in per-lane uint4 order -------------------
// uint4 index e = ((kw*2 + m)*8 + ks)*32 + lane
__global__ void build_afr16(const float* __restrict__ wgt) {
    int e = blockIdx.x * 256 + threadIdx.x;
    if (e >= AFR_U4) return;
    int lane = e & 31;
    int ks   = (e >> 5) & 7;
    int m    = (e >> 8) & 1;
    int kw   = e >> 9;
    int g = lane >> 2, t = lane & 3;
    int o0 = m * 16 + g;
    int c0 = ks * 16 + 2 * t;
    auto W = [&](int o, int c) {
        return __float2half_rn(wgt[(o * 128 + c) * 3 + kw]);
    };
    __half2 a0 = __halves2half2(W(o0,     c0),     W(o0,     c0 + 1));
    __half2 a1 = __halves2half2(W(o0 + 8, c0),     W(o0 + 8, c0 + 1));
    __half2 a2 = __halves2half2(W(o0,     c0 + 8), W(o0,     c0 + 9));
    __half2 a3 = __halves2half2(W(o0 + 8, c0 + 8), W(o0 + 8, c0 + 9));
    g_afr[e] = make_uint4(h2bits(a0), h2bits(a1), h2bits(a2), h2bits(a3));
}

__global__ __launch_bounds__(256, 3)
void conv1x3_shift_f16_v5(const float* __restrict__ x,
                          float* __restrict__ out) {
    extern __shared__ char smem[];
    __half2* xs  = reinterpret_cast<__half2*>(smem);            // [2][64][72]
    uint4*   afs = reinterpret_cast<uint4*>(smem + XS_BYTES);   // [1536]

    const int tid = threadIdx.x;
    const int blk = blockIdx.x;

    // --- copy A table to smem (independent LDGs, overlaps x staging) -------
    #pragma unroll
    for (int e = 0; e < 6; e++) afs[tid + 256 * e] = g_afr[tid + 256 * e];

    // --- zero pad slots: half2 idx 3 (w=-1) and 60 (w=56) ------------------
    if (tid < ROWS_PER_BLK * 64) {
        xs[tid * WSTRIDE + 3]  = __float2half2_rn(0.f);
        xs[tid * WSTRIDE + 60] = __float2half2_rn(0.f);
    }

    // --- stage 2 x rows as half2 channel pairs, batched for MLP ------------
    // thread = (r, c2, qg): 7 consecutive float4 from plane 2*c2 and 7 from
    // plane 2*c2+1 (qg selects first/second 28 floats of the 56-wide row).
    {
        const int sr  = tid >> 7;          // 0..1
        const int c2  = (tid >> 1) & 63;   // 0..63
        const int qg  = tid & 1;           // 0..1
        const int R   = blk * ROWS_PER_BLK + sr;
        const int n   = R / 56;
        const int h   = R - n * 56;
        const int hsrc = h ? (h - 1) : 55;     // roll(+1) on H
        const float* pa =
            x + ((size_t)(n * 128 + 2 * c2) * 56 + hsrc) * 56 + qg * 28;
        const float* pb = pa + CH_STRIDE;

        float4 va[7], vb[7];
        #pragma unroll
        for (int u = 0; u < 7; u++)
            va[u] = *reinterpret_cast<const float4*>(pa + 4 * u);
        #pragma unroll
        for (int u = 0; u < 7; u++)
            vb[u] = *reinterpret_cast<const float4*>(pb + 4 * u);

        // dst uint4 index: (r*64+c2)*18 + 1 + qg*7 + u  -> conflict-free STS
        uint4* dst = reinterpret_cast<uint4*>(xs) +
                     (sr * 64 + c2) * 18 + 1 + qg * 7;
        #pragma unroll
        for (int u = 0; u < 7; u++) {
            dst[u] = make_uint4(h2bits(__floats2half2_rn(va[u].x, vb[u].x)),
                                h2bits(__floats2half2_rn(va[u].y, vb[u].y)),
                                h2bits(__floats2half2_rn(va[u].z, vb[u].z)),
                                h2bits(__floats2half2_rn(va[u].w, vb[u].w)));
        }
    }
    __syncthreads();

    // --- warp = (row r, quarter q4); warp owns w-tiles {2q4, 2q4+1} --------
    const int warp = tid >> 5;
    const int lane = tid & 31;
    const int r    = warp >> 2;        // 0..1
    const int q4   = warp & 3;         // 0..3
    const int g    = lane >> 2;        // 0..7
    const int t    = lane & 3;         // 0..3

    const int ntile = (q4 == 3) ? 1 : 2;   // tile 7 doesn't exist (W=56)

    int wcol[2];
    #pragma unroll
    for (int j = 0; j < 2; j++) wcol[j] = g + 8 * (2 * q4 + j);

    float acc[2][2][4];
    #pragma unroll
    for (int m = 0; m < 2; m++)
        #pragma unroll
        for (int j = 0; j < 2; j++)
            #pragma unroll
            for (int v = 0; v < 4; v++) acc[m][j][v] = 0.f;

    const __half2* xrow = xs + r * XS_H2_ROW;

    #pragma unroll 2
    for (int ks = 0; ks < 8; ks++) {
        // B rows: b0 -> c2 = 8ks + t, b1 -> c2 = 8ks + t + 4.
        // smem idx = c2*WSTRIDE + 3 + wcol + kw  (bank = 8t + g + const)
        const __half2* p0 = xrow + (8 * ks + t) * WSTRIDE + 3;
        const __half2* p1 = p0 + 4 * WSTRIDE;

        unsigned bv0[2][3], bv1[2][3];
        #pragma unroll
        for (int j = 0; j < 2; j++) {
            if (j >= ntile) continue;
            #pragma unroll
            for (int kw = 0; kw < 3; kw++) {
                bv0[j][kw] = h2bits(p0[wcol[j] + kw]);
                bv1[j][kw] = h2bits(p1[wcol[j] + kw]);
            }
        }
        #pragma unroll
        for (int kw = 0; kw < 3; kw++) {
            uint4 a0 = afs[((kw * 2 + 0) * 8 + ks) * 32 + lane];
            uint4 a1 = afs[((kw * 2 + 1) * 8 + ks) * 32 + lane];
            #pragma unroll
            for (int j = 0; j < 2; j++) {
                if (j >= ntile) continue;
                mma_f16(acc[0][j], a0, bv0[j][kw], bv1[j][kw]);
                mma_f16(acc[1][j], a1, bv0[j][kw], bv1[j][kw]);
            }
        }
    }

    // --- epilogue: C frag c0=(g,2t) c1=(g,2t+1) c2=(g+8,2t) c3=(g+8,2t+1) --
    {
        int R = blk * ROWS_PER_BLK + r;
        int n = R / 56;
        int h = R - n * 56;
        #pragma unroll
        for (int m = 0; m < 2; m++) {
            int o0 = m * 16 + g;
            #pragma unroll
            for (int j = 0; j < 2; j++) {
                if (j >= ntile) continue;
                int wc = 8 * (2 * q4 + j) + 2 * t;   // even, < 56
                float* p0 = out + ((size_t)n * 32 + o0) * CH_STRIDE + h * 56 + wc;
                *reinterpret_cast<float2*>(p0) =
                    make_float2(acc[m][j][0], acc[m][j][1]);
                float* p1 = p0 + 8 * CH_STRIDE;       // o0 + 8
                *reinterpret_cast<float2*>(p1) =
                    make_float2(acc[m][j][2], acc[m][j][3]);
            }
        }
    }
}

extern "C" void kernel_launch(void* const* d_in, const int* in_sizes, int n_in,
                              void* d_out, int out_size) {
    const float* x   = (const float*)d_in[0];   // (128,128,56,56) f32
    const float* wgt = (const float*)d_in[1];   // (32,128,3) f32
    float*       out = (float*)d_out;           // (128,32,56,56) f32

    cudaFuncSetAttribute(conv1x3_shift_f16_v5,
                         cudaFuncAttributeMaxDynamicSharedMemorySize,
                         SMEM_BYTES);

    build_afr16<<<(AFR_U4 + 255) / 256, 256>>>(wgt);
    // 7168 (n,h) rows / 2 rows per block = 3584 blocks
    conv1x3_shift_f16_v5<<<3584, 256, SMEM_BYTES>>>(x, out);
}

// round 15
// speedup vs baseline: 1.6322x; 1.0443x over previous
#include <cuda_runtime.h>
#include <cuda_fp16.h>
#include <cstdint>

// ---------------------------------------------------------------------------
// out[n,o,h,w] = sum_{c,kw} x[n,c,(h-1)%56, w+kw-1] * wgt[o,c,kw]
// N=128, C=128, H=W=56, O=32, KW=3 (pad W by 1 each side).
// v6 = v5 (fp16 m16n8k16, half2 channel-pair smem, smem A table, MLP-batched
// staging) with warp layout 2 warps/row x 4 rows/block: each warp covers
// 4 (or 3) n8-tiles instead of 2, halving A-fragment LDS wavefronts per unit
// of output (the measured l1tex binder). smem = 72KB x + 24KB A = 96KB ->
// 2 CTAs/SM, 16 warps.
// ---------------------------------------------------------------------------

namespace {

constexpr int ROWS_PER_BLK = 4;                 // (n,h) rows per block
constexpr int WSTRIDE      = 72;                // half2 per c2-row (72%32==8)
constexpr int XS_H2_ROW    = 64 * WSTRIDE;      // 4608 half2 per (n,h) row
constexpr int XS_BYTES     = ROWS_PER_BLK * XS_H2_ROW * 4;   // 73728
constexpr int AFR_U4       = 3 * 2 * 8 * 32;    // kw * mtile * ks * lane = 1536
constexpr int AFR_BYTES    = AFR_U4 * 16;       // 24576
constexpr int SMEM_BYTES   = XS_BYTES + AFR_BYTES;           // 98304
constexpr int CH_STRIDE    = 56 * 56;           // 3136

__device__ __align__(16) uint4 g_afr[AFR_U4];   // weight fragments (fp16 bits)

__device__ __forceinline__ unsigned h2bits(__half2 h) {
    return *reinterpret_cast<unsigned*>(&h);
}

__device__ __forceinline__ void mma_f16(float d[4], const uint4& a,
                                        unsigned b0, unsigned b1) {
    asm volatile(
        "mma.sync.aligned.m16n8k16.row.col.f32.f16.f16.f32 "
        "{%0,%1,%2,%3}, {%4,%5,%6,%7}, {%8,%9}, {%0,%1,%2,%3};"
        : "+f"(d[0]), "+f"(d[1]), "+f"(d[2]), "+f"(d[3])
        : "r"(a.x), "r"(a.y), "r"(a.z), "r"(a.w), "r"(b0), "r"(b1));
}

} // namespace

// --- prep: build fp16 A fragments in per-lane uint4 order -------------------
// uint4 index e = ((kw*2 + m)*8 + ks)*32 + lane
__global__ void build_afr16(const float* __restrict__ wgt) {
    int e = blockIdx.x * 256 + threadIdx.x;
    if (e >= AFR_U4) return;
    int lane = e & 31;
    int ks   = (e >> 5) & 7;
    int m    = (e >> 8) & 1;
    int kw   = e >> 9;
    int g = lane >> 2, t = lane & 3;
    int o0 = m * 16 + g;
    int c0 = ks * 16 + 2 * t;
    auto W = [&](int o, int c) {
        return __float2half_rn(wgt[(o * 128 + c) * 3 + kw]);
    };
    __half2 a0 = __halves2half2(W(o0,     c0),     W(o0,     c0 + 1));
    __half2 a1 = __halves2half2(W(o0 + 8, c0),     W(o0 + 8, c0 + 1));
    __half2 a2 = __halves2half2(W(o0,     c0 + 8), W(o0,     c0 + 9));
    __half2 a3 = __halves2half2(W(o0 + 8, c0 + 8), W(o0 + 8, c0 + 9));
    g_afr[e] = make_uint4(h2bits(a0), h2bits(a1), h2bits(a2), h2bits(a3));
}

__global__ __launch_bounds__(256, 2)
void conv1x3_shift_f16_v6(const float* __restrict__ x,
                          float* __restrict__ out) {
    extern __shared__ char smem[];
    __half2* xs  = reinterpret_cast<__half2*>(smem);            // [4][64][72]
    uint4*   afs = reinterpret_cast<uint4*>(smem + XS_BYTES);   // [1536]

    const int tid = threadIdx.x;
    const int blk = blockIdx.x;

    // --- copy A table to smem (independent LDGs, overlaps x staging) -------
    #pragma unroll
    for (int e = 0; e < 6; e++) afs[tid + 256 * e] = g_afr[tid + 256 * e];

    // --- zero pad slots: half2 idx 3 (w=-1) and 60 (w=56); 256 slots -------
    xs[tid * WSTRIDE + 3]  = __float2half2_rn(0.f);
    xs[tid * WSTRIDE + 60] = __float2half2_rn(0.f);

    // --- stage 4 x rows as half2 channel pairs, batched for MLP ------------
    // slot = (sr, c2, qg): 7 consecutive float4 from plane 2*c2 and 7 from
    // plane 2*c2+1 (qg = first/second 28 floats). 512 slots over 2 passes.
    #pragma unroll
    for (int it = 0; it < 2; it++) {
        const int idx = tid + 256 * it;
        const int sr  = idx >> 7;          // 0..3
        const int c2  = (idx >> 1) & 63;   // 0..63
        const int qg  = idx & 1;           // 0..1
        const int R   = blk * ROWS_PER_BLK + sr;
        const int n   = R / 56;
        const int h   = R - n * 56;
        const int hsrc = h ? (h - 1) : 55;     // roll(+1) on H
        const float* pa =
            x + ((size_t)(n * 128 + 2 * c2) * 56 + hsrc) * 56 + qg * 28;
        const float* pb = pa + CH_STRIDE;

        float4 va[7], vb[7];
        #pragma unroll
        for (int u = 0; u < 7; u++)
            va[u] = *reinterpret_cast<const float4*>(pa + 4 * u);
        #pragma unroll
        for (int u = 0; u < 7; u++)
            vb[u] = *reinterpret_cast<const float4*>(pb + 4 * u);

        uint4* dst = reinterpret_cast<uint4*>(xs) +
                     (sr * 64 + c2) * 18 + 1 + qg * 7;
        #pragma unroll
        for (int u = 0; u < 7; u++) {
            dst[u] = make_uint4(h2bits(__floats2half2_rn(va[u].x, vb[u].x)),
                                h2bits(__floats2half2_rn(va[u].y, vb[u].y)),
                                h2bits(__floats2half2_rn(va[u].z, vb[u].z)),
                                h2bits(__floats2half2_rn(va[u].w, vb[u].w)));
        }
    }
    __syncthreads();

    // --- warp = (row r, half). half 0 -> w-tiles 0..3, half 1 -> 4..6 ------
    const int warp = tid >> 5;
    const int lane = tid & 31;
    const int r    = warp >> 1;        // 0..3
    const int half = warp & 1;         // 0..1
    const int g    = lane >> 2;        // 0..7
    const int t    = lane & 3;         // 0..3

    int wcol[4];
    #pragma unroll
    for (int j = 0; j < 4; j++) wcol[j] = g + 8 * (half * 4 + j);

    float acc[2][4][4];
    #pragma unroll
    for (int m = 0; m < 2; m++)
        #pragma unroll
        for (int j = 0; j < 4; j++)
            #pragma unroll
            for (int v = 0; v < 4; v++) acc[m][j][v] = 0.f;

    const __half2* xrow = xs + r * XS_H2_ROW;

    #pragma unroll 2
    for (int ks = 0; ks < 8; ks++) {
        // B rows: b0 -> c2 = 8ks + t, b1 -> c2 = 8ks + t + 4.
        // smem idx = c2*WSTRIDE + 3 + wcol + kw  (bank = 8t + g + const)
        const __half2* p0 = xrow + (8 * ks + t) * WSTRIDE + 3;
        const __half2* p1 = p0 + 4 * WSTRIDE;

        unsigned bv0[4][3], bv1[4][3];
        #pragma unroll
        for (int j = 0; j < 4; j++) {
            if (half && j == 3) continue;      // tile 7 doesn't exist (W=56)
            #pragma unroll
            for (int kw = 0; kw < 3; kw++) {
                bv0[j][kw] = h2bits(p0[wcol[j] + kw]);
                bv1[j][kw] = h2bits(p1[wcol[j] + kw]);
            }
        }
        #pragma unroll
        for (int kw = 0; kw < 3; kw++) {
            uint4 a0 = afs[((kw * 2 + 0) * 8 + ks) * 32 + lane];
            uint4 a1 = afs[((kw * 2 + 1) * 8 + ks) * 32 + lane];
            #pragma unroll
            for (int j = 0; j < 4; j++) {
                if (half && j == 3) continue;
                mma_f16(acc[0][j], a0, bv0[j][kw], bv1[j][kw]);
                mma_f16(acc[1][j], a1, bv0[j][kw], bv1[j][kw]);
            }
        }
    }

    // --- epilogue: C frag c0=(g,2t) c1=(g,2t+1) c2=(g+8,2t) c3=(g+8,2t+1) --
    {
        int R = blk * ROWS_PER_BLK + r;
        int n = R / 56;
        int h = R - n * 56;
        #pragma unroll
        for (int m = 0; m < 2; m++) {
            int o0 = m * 16 + g;
            #pragma unroll
            for (int j = 0; j < 4; j++) {
                if (half && j == 3) continue;
                int wc = 8 * (half * 4 + j) + 2 * t;   // even, < 56
                float* p0 = out + ((size_t)n * 32 + o0) * CH_STRIDE + h * 56 + wc;
                *reinterpret_cast<float2*>(p0) =
                    make_float2(acc[m][j][0], acc[m][j][1]);
                float* p1 = p0 + 8 * CH_STRIDE;         // o0 + 8
                *reinterpret_cast<float2*>(p1) =
                    make_float2(acc[m][j][2], acc[m][j][3]);
            }
        }
    }
}

extern "C" void kernel_launch(void* const* d_in, const int* in_sizes, int n_in,
                              void* d_out, int out_size) {
    const float* x   = (const float*)d_in[0];   // (128,128,56,56) f32
    const float* wgt = (const float*)d_in[1];   // (32,128,3) f32
    float*       out = (float*)d_out;           // (128,32,56,56) f32

    cudaFuncSetAttribute(conv1x3_shift_f16_v6,
                         cudaFuncAttributeMaxDynamicSharedMemorySize,
                         SMEM_BYTES);

    build_afr16<<<(AFR_U4 + 255) / 256, 256>>>(wgt);
    // 7168 (n,h) rows / 4 rows per block = 1792 blocks
    conv1x3_shift_f16_v6<<<1792, 256, SMEM_BYTES>>>(x, out);
}